// round 4
// baseline (speedup 1.0000x reference)
#include <cuda_runtime.h>
#include <cuda_bf16.h>
#include <stdint.h>

#define BATCH 16
#define LQ    512
#define LK    4096
#define DM    128

// CLIP * tanh(s) / sqrt(128) -> logit = (10/sqrt(128)) * tanh(s)
#define LOGIT_SCALE 0.88388347648318447f

// Scratch for projected q/k (device globals; no allocation allowed).
__device__ __align__(16) float g_kproj[(size_t)BATCH * LK * DM];   // 33.5 MB
__device__ __align__(16) float g_qproj[(size_t)BATCH * LQ * DM];   // 4 MB

// ---------------------------------------------------------------------------
// helpers
// ---------------------------------------------------------------------------
__device__ __forceinline__ void fma2(unsigned long long& d,
                                     unsigned long long a,
                                     unsigned long long b) {
    // packed 2-wide fp32 FMA (sm_100+): d.lo += a.lo*b.lo ; d.hi += a.hi*b.hi
    asm("fma.rn.f32x2 %0, %1, %2, %0;" : "+l"(d) : "l"(a), "l"(b));
}

__device__ __forceinline__ float2 unpack2(unsigned long long u) {
    float2 f;
    asm("mov.b64 {%0, %1}, %2;" : "=f"(f.x), "=f"(f.y) : "l"(u));
    return f;
}

// Accurate tanh via expf (expf stays accurate enough even under fast-math;
// MUFU.TANH approx error would be amplified by the *8.84 logit scale).
__device__ __forceinline__ float tanh_acc(float x) {
    float ax = fabsf(x);
    float e  = expf(-2.0f * ax);          // in (0, 1]
    float t  = (1.0f - e) / (1.0f + e);
    return copysignf(t, x);
}

// ---------------------------------------------------------------------------
// Projection: Y[m][e] = sum_d X[m][d] * W[d][e] + b[e]     (W stored [in,out])
// CTA: 64 rows x 128 cols. 256 threads: tx(0..15) -> 8 cols, ty(0..15) -> 4 rows.
// X tile staged in smem (padded stride 132 to dodge bank conflicts),
// W + bias read through L1 (64 KB, fully L1-resident per SM).
// ---------------------------------------------------------------------------
__global__ __launch_bounds__(256)
void proj_kernel(const float* __restrict__ X,
                 const float* __restrict__ W,
                 const float* __restrict__ bias,
                 int which)   // 0 -> g_qproj, 1 -> g_kproj
{
    float* __restrict__ Y = which ? g_kproj : g_qproj;

    __shared__ __align__(16) float Xs[64 * 132];

    const int m0  = blockIdx.x * 64;
    const int tid = threadIdx.x;

    // Stage 64x128 X tile (2048 float4 / 256 threads = 8 each), coalesced.
#pragma unroll
    for (int i = 0; i < 8; ++i) {
        int idx = tid + i * 256;          // float4 index
        int m   = idx >> 5;
        int d4  = idx & 31;
        float4 v = *(const float4*)(X + (size_t)(m0 + m) * DM + d4 * 4);
        *(float4*)(Xs + m * 132 + d4 * 4) = v;
    }
    __syncthreads();

    const int tx = tid & 15;
    const int ty = tid >> 4;
    const int c0 = tx * 8;

    float acc[4][8];
#pragma unroll
    for (int r = 0; r < 4; ++r)
#pragma unroll
        for (int c = 0; c < 8; ++c) acc[r][c] = 0.0f;

    for (int d4 = 0; d4 < 32; ++d4) {
        const int d = d4 * 4;
        float4 w0[4], w1[4];
#pragma unroll
        for (int j = 0; j < 4; ++j) {
            w0[j] = *(const float4*)(W + (size_t)(d + j) * DM + c0);
            w1[j] = *(const float4*)(W + (size_t)(d + j) * DM + c0 + 4);
        }
#pragma unroll
        for (int r = 0; r < 4; ++r) {
            float4 x4 = *(const float4*)(Xs + (ty * 4 + r) * 132 + d);
            float xv[4] = {x4.x, x4.y, x4.z, x4.w};
#pragma unroll
            for (int j = 0; j < 4; ++j) {
                acc[r][0] += xv[j] * w0[j].x;
                acc[r][1] += xv[j] * w0[j].y;
                acc[r][2] += xv[j] * w0[j].z;
                acc[r][3] += xv[j] * w0[j].w;
                acc[r][4] += xv[j] * w1[j].x;
                acc[r][5] += xv[j] * w1[j].y;
                acc[r][6] += xv[j] * w1[j].z;
                acc[r][7] += xv[j] * w1[j].w;
            }
        }
    }

    float4 b0 = *(const float4*)(bias + c0);
    float4 b1 = *(const float4*)(bias + c0 + 4);
#pragma unroll
    for (int r = 0; r < 4; ++r) {
        size_t row = (size_t)(m0 + ty * 4 + r) * DM;
        float4 o0 = make_float4(acc[r][0] + b0.x, acc[r][1] + b0.y,
                                acc[r][2] + b0.z, acc[r][3] + b0.w);
        float4 o1 = make_float4(acc[r][4] + b1.x, acc[r][5] + b1.y,
                                acc[r][6] + b1.z, acc[r][7] + b1.w);
        *(float4*)(Y + row + c0)     = o0;
        *(float4*)(Y + row + c0 + 4) = o1;
    }
}

// ---------------------------------------------------------------------------
// Attention: CTA = (32 q-rows, one batch) x all 4096 k-cols.
// 16 passes of 256 cols; each thread owns one k-row per pass.
// Score GEMM in packed f32x2 (FFMA2): q tile broadcast from smem (LDS.128,
// all lanes same address -> conflict-free), k streamed from L2-resident scratch.
// e = mask ? exp(logit) : 0 written to out; row sums reduced (shfl + smem
// atomics); final in-CTA normalization pass (re-reads are L2-hot).
// No running max needed: |logit| <= 8.84, exp range safe in fp32.
// ---------------------------------------------------------------------------
__global__ __launch_bounds__(256)
void attn_kernel(const int* __restrict__ mask, float* __restrict__ out)
{
    const int b   = blockIdx.y;
    const int q0  = blockIdx.x * 32;
    const int tid = threadIdx.x;
    const int lane = tid & 31;

    __shared__ __align__(16) float qs[32 * DM];   // 16 KB
    __shared__ float rsum_s[32];

    // load q tile (32x128 floats = 1024 float4 / 256 threads)
#pragma unroll
    for (int i = 0; i < 4; ++i) {
        int idx = tid + i * 256;
        *(float4*)(qs + idx * 4) =
            *(const float4*)(g_qproj + ((size_t)b * LQ + q0) * DM + idx * 4);
    }
    if (tid < 32) rsum_s[tid] = 0.0f;
    __syncthreads();

    for (int pass = 0; pass < 16; ++pass) {
        const int n = pass * 256 + tid;
        const ulonglong2* kp =
            (const ulonglong2*)(g_kproj + ((size_t)b * LK + n) * DM);

        unsigned long long acc[32];
#pragma unroll
        for (int q = 0; q < 32; ++q) acc[q] = 0ull;

        ulonglong2 kc = kp[0];
#pragma unroll 2
        for (int d4 = 0; d4 < 32; ++d4) {
            ulonglong2 kn = kc;
            if (d4 < 31) kn = kp[d4 + 1];       // prefetch next 16B
            const ulonglong2* qp = (const ulonglong2*)qs + d4;
#pragma unroll
            for (int q = 0; q < 32; ++q) {
                ulonglong2 q2 = qp[q * 32];     // warp-wide broadcast
                fma2(acc[q], q2.x, kc.x);
                fma2(acc[q], q2.y, kc.y);
            }
            kc = kn;
        }

        // epilogue: tanh-clip -> exp -> mask -> store + row-sum reduce
        const size_t base = ((size_t)b * LQ + q0) * LK + n;
#pragma unroll 8
        for (int q = 0; q < 32; ++q) {
            float2 a = unpack2(acc[q]);
            float  s = a.x + a.y;
            float  t = tanh_acc(s);
            float  e = 0.0f;
            if (mask[base + (size_t)q * LK] != 0)
                e = expf(LOGIT_SCALE * t);
            out[base + (size_t)q * LK] = e;

            float v = e;
            v += __shfl_xor_sync(0xffffffffu, v, 16);
            v += __shfl_xor_sync(0xffffffffu, v, 8);
            v += __shfl_xor_sync(0xffffffffu, v, 4);
            v += __shfl_xor_sync(0xffffffffu, v, 2);
            v += __shfl_xor_sync(0xffffffffu, v, 1);
            if (lane == 0) atomicAdd(&rsum_s[q], v);
        }
    }

    __syncthreads();   // row sums complete + global e-writes visible in block

    // normalize: warp w -> rows w*4 .. w*4+3
    const int w = tid >> 5;
#pragma unroll
    for (int r = 0; r < 4; ++r) {
        int q = w * 4 + r;
        float inv = 1.0f / rsum_s[q];
        float4* row = (float4*)(out + ((size_t)b * LQ + q0 + q) * LK);
        for (int i = lane; i < LK / 4; i += 32) {
            float4 v = row[i];
            v.x *= inv; v.y *= inv; v.z *= inv; v.w *= inv;
            row[i] = v;
        }
    }
}

// ---------------------------------------------------------------------------
// launch
// ---------------------------------------------------------------------------
extern "C" void kernel_launch(void* const* d_in, const int* in_sizes, int n_in,
                              void* d_out, int out_size)
{
    (void)in_sizes; (void)n_in; (void)out_size;
    const float* query = (const float*)d_in[0];   // [16,512,128]
    const float* key   = (const float*)d_in[1];   // [16,4096,128]
    const int*   mask  = (const int*)  d_in[2];   // [16,512,4096]
    const float* Wq    = (const float*)d_in[3];   // [128,128] (in,out)
    const float* bq    = (const float*)d_in[4];   // [128]
    const float* Wk    = (const float*)d_in[5];
    const float* bk    = (const float*)d_in[6];
    float* out = (float*)d_out;

    // projections (default stream serializes before attention)
    proj_kernel<<<(BATCH * LQ) / 64, 256>>>(query, Wq, bq, /*which=*/0);
    proj_kernel<<<(BATCH * LK) / 64, 256>>>(key,   Wk, bk, /*which=*/1);

    dim3 grid(LQ / 32, BATCH);
    attn_kernel<<<grid, 256>>>(mask, out);
}

// round 5
// speedup vs baseline: 3.5511x; 3.5511x over previous
#include <cuda_runtime.h>
#include <cuda_bf16.h>
#include <stdint.h>

#define BATCH 16
#define LQ    512
#define LK    4096
#define DM    128

// y = 2*log2(e) * s  so that 2^y = e^{2s}
#define TWO_LOG2E 2.8853900817779268f
// C*log2(e), C = 10/sqrt(128)
#define Z_SCALE   1.2751743093739637f

// Scratch (device globals; allocation is forbidden).
__device__ __align__(16) float g_kproj[(size_t)BATCH * LK * DM];   // 33.5 MB
__device__ __align__(16) float g_qproj[(size_t)BATCH * LQ * DM];   // 4 MB
__device__ float g_rowsum[BATCH * LQ];                              // 32 KB

// ---------------------------------------------------------------------------
// helpers
// ---------------------------------------------------------------------------
__device__ __forceinline__ void fma2(unsigned long long& d,
                                     unsigned long long a,
                                     unsigned long long b) {
    asm("fma.rn.f32x2 %0, %1, %2, %0;" : "+l"(d) : "l"(a), "l"(b));
}

__device__ __forceinline__ float2 unpack2(unsigned long long u) {
    float2 f;
    asm("mov.b64 {%0, %1}, %2;" : "=f"(f.x), "=f"(f.y) : "l"(u));
    return f;
}

// exp2 on the FMA pipe only: magic-number round, degree-5 poly, exponent add.
// Valid for y in ~[-120, 120]; rel err ~1e-7.
__device__ __forceinline__ float fast_exp2(float y) {
    float t  = y + 12582912.0f;                      // 1.5 * 2^23 : RN to int
    int   n  = __float_as_int(t) - 0x4B400000;       // integer part
    float f  = y - (t - 12582912.0f);                // f in [-0.5, 0.5], exact
    float p  =            1.3333558146e-3f;
    p = fmaf(p, f,        9.6181291076e-3f);
    p = fmaf(p, f,        5.5504108664e-2f);
    p = fmaf(p, f,        2.4022650696e-1f);
    p = fmaf(p, f,        6.9314718056e-1f);
    p = fmaf(p, f,        1.0f);
    return __int_as_float(__float_as_int(p) + (n << 23));
}

// 1/a without MUFU: bit-trick seed + 3 Newton steps (err ~1e-10 rel).
// a must be positive normal (here a = 1+u, a in [1, 2^31)).
__device__ __forceinline__ float fast_rcp(float a) {
    float x = __int_as_float(0x7EF311C3 - __float_as_int(a));
    x = x * fmaf(-a, x, 2.0f);
    x = x * fmaf(-a, x, 2.0f);
    x = x * fmaf(-a, x, 2.0f);
    return x;
}

// exp(C * tanh(s)) with zero MUFU:
//   tanh(s) = 1 - 2/(1 + e^{2s}),  e^{2s} = 2^{2 log2e s}
__device__ __forceinline__ float attn_weight(float s) {
    float y = fminf(fmaxf(TWO_LOG2E * s, -30.0f), 30.0f);
    float u = fast_exp2(y);
    float r = fast_rcp(1.0f + u);
    float t = fmaf(-2.0f, r, 1.0f);          // tanh(s), abs err < 1e-6
    return fast_exp2(Z_SCALE * t);           // in [0.413, 2.42]
}

// ---------------------------------------------------------------------------
// Projection: Y[m][e] = sum_d X[m][d] * W[d][e] + b[e]  (unchanged from R4)
// ---------------------------------------------------------------------------
__global__ __launch_bounds__(256)
void proj_kernel(const float* __restrict__ X,
                 const float* __restrict__ W,
                 const float* __restrict__ bias,
                 int which)
{
    float* __restrict__ Y = which ? g_kproj : g_qproj;

    __shared__ __align__(16) float Xs[64 * 132];

    const int m0  = blockIdx.x * 64;
    const int tid = threadIdx.x;

#pragma unroll
    for (int i = 0; i < 8; ++i) {
        int idx = tid + i * 256;
        int m   = idx >> 5;
        int d4  = idx & 31;
        float4 v = *(const float4*)(X + (size_t)(m0 + m) * DM + d4 * 4);
        *(float4*)(Xs + m * 132 + d4 * 4) = v;
    }
    __syncthreads();

    const int tx = tid & 15;
    const int ty = tid >> 4;
    const int c0 = tx * 8;

    float acc[4][8];
#pragma unroll
    for (int r = 0; r < 4; ++r)
#pragma unroll
        for (int c = 0; c < 8; ++c) acc[r][c] = 0.0f;

    for (int d4 = 0; d4 < 32; ++d4) {
        const int d = d4 * 4;
        float4 w0[4], w1[4];
#pragma unroll
        for (int j = 0; j < 4; ++j) {
            w0[j] = *(const float4*)(W + (size_t)(d + j) * DM + c0);
            w1[j] = *(const float4*)(W + (size_t)(d + j) * DM + c0 + 4);
        }
#pragma unroll
        for (int r = 0; r < 4; ++r) {
            float4 x4 = *(const float4*)(Xs + (ty * 4 + r) * 132 + d);
            float xv[4] = {x4.x, x4.y, x4.z, x4.w};
#pragma unroll
            for (int j = 0; j < 4; ++j) {
                acc[r][0] += xv[j] * w0[j].x;
                acc[r][1] += xv[j] * w0[j].y;
                acc[r][2] += xv[j] * w0[j].z;
                acc[r][3] += xv[j] * w0[j].w;
                acc[r][4] += xv[j] * w1[j].x;
                acc[r][5] += xv[j] * w1[j].y;
                acc[r][6] += xv[j] * w1[j].z;
                acc[r][7] += xv[j] * w1[j].w;
            }
        }
    }

    float4 b0 = *(const float4*)(bias + c0);
    float4 b1 = *(const float4*)(bias + c0 + 4);
#pragma unroll
    for (int r = 0; r < 4; ++r) {
        size_t row = (size_t)(m0 + ty * 4 + r) * DM;
        float4 o0 = make_float4(acc[r][0] + b0.x, acc[r][1] + b0.y,
                                acc[r][2] + b0.z, acc[r][3] + b0.w);
        float4 o1 = make_float4(acc[r][4] + b1.x, acc[r][5] + b1.y,
                                acc[r][6] + b1.z, acc[r][7] + b1.w);
        *(float4*)(Y + row + c0)     = o0;
        *(float4*)(Y + row + c0 + 4) = o1;
    }
}

// ---------------------------------------------------------------------------
// zero the row-sum accumulator (graph replays re-enter with stale values)
// ---------------------------------------------------------------------------
__global__ void zero_rowsum_kernel() {
    int i = blockIdx.x * blockDim.x + threadIdx.x;
    if (i < BATCH * LQ) g_rowsum[i] = 0.0f;
}

// ---------------------------------------------------------------------------
// Attention phase 1: register-tiled GEMM (f32x2 along d) + MUFU-free epilogue.
// CTA tile: 128 q x 64 k. 256 threads; thread (tx = tid&15, ty = tid>>4)
// owns q rows ty*8..+7 and k cols {tx, tx+16, tx+32, tx+48}.
// acc[r][c] is a ull: lo = even-d partial dot, hi = odd-d partial dot.
// smem: Qs[128][32]f4, Ks[64][32]f4, quad-XOR-swizzled for <=2-phase LDS.128.
// Writes e = mask * exp(C tanh(s)) to out; row sums -> g_rowsum via REDG.
// ---------------------------------------------------------------------------
__global__ __launch_bounds__(256, 2)
void attn_kernel(const int* __restrict__ mask, float* __restrict__ out)
{
    extern __shared__ float4 smem4[];
    float4* Qs = smem4;              // [128][32] float4, col j stored at j^((row>>3)&7)
    float4* Ks = smem4 + 128 * 32;   // [64][32]  float4, col j stored at j^(row&7)

    const int b   = blockIdx.z;
    const int q0  = blockIdx.y * 128;
    const int n0  = blockIdx.x * 64;
    const int tid = threadIdx.x;
    const int tx  = tid & 15;
    const int ty  = tid >> 4;

    // ---- stage tiles: 192 rows x 32 f4; one warp fills exactly one row ----
    const float4* qsrc = (const float4*)(g_qproj + ((size_t)b * LQ + q0) * DM);
    const float4* ksrc = (const float4*)(g_kproj + ((size_t)b * LK + n0) * DM);
#pragma unroll
    for (int i = 0; i < 24; ++i) {
        int idx = tid + i * 256;
        int row = idx >> 5;
        int j   = idx & 31;
        if (row < 128) {
            Qs[row * 32 + (j ^ ((row >> 3) & 7))] = qsrc[row * 32 + j];
        } else {
            int kr = row - 128;
            Ks[kr * 32 + (j ^ (kr & 7))] = ksrc[kr * 32 + j];
        }
    }
    __syncthreads();

    // ---- GEMM ----
    unsigned long long acc[8][4];
#pragma unroll
    for (int r = 0; r < 8; ++r)
#pragma unroll
        for (int c = 0; c < 4; ++c) acc[r][c] = 0ull;

    const int sq = ty & 7;
    const int sk = tx & 7;
    const float4* qbase = Qs + (ty * 8) * 32;
    const float4* kbase = Ks + tx * 32;

#pragma unroll 4
    for (int d4 = 0; d4 < 32; ++d4) {
        const int dq = d4 ^ sq;
        const int dk = d4 ^ sk;
        ulonglong2 kv[4];
#pragma unroll
        for (int c = 0; c < 4; ++c)
            kv[c] = *(const ulonglong2*)(kbase + c * 512 + dk);   // 16 rows apart
#pragma unroll
        for (int r = 0; r < 8; ++r) {
            ulonglong2 qv = *(const ulonglong2*)(qbase + r * 32 + dq);
#pragma unroll
            for (int c = 0; c < 4; ++c) {
                fma2(acc[r][c], qv.x, kv[c].x);   // d, d+1
                fma2(acc[r][c], qv.y, kv[c].y);   // d+2, d+3
            }
        }
    }

    // ---- epilogue: weight, mask, store, row-sum ----
    const int lane = tid & 31;
#pragma unroll
    for (int r = 0; r < 8; ++r) {
        const int    q     = q0 + ty * 8 + r;
        const size_t obase = ((size_t)b * LQ + q) * LK + n0 + tx;
        float rs = 0.0f;
#pragma unroll
        for (int c = 0; c < 4; ++c) {
            float2 p = unpack2(acc[r][c]);
            float  s = p.x + p.y;
            float  h = attn_weight(s);
            float  e = (mask[obase + c * 16] != 0) ? h : 0.0f;
            out[obase + c * 16] = e;
            rs += e;
        }
        // reduce across the 16 tx lanes (ty constant within each half-warp)
        rs += __shfl_xor_sync(0xffffffffu, rs, 8);
        rs += __shfl_xor_sync(0xffffffffu, rs, 4);
        rs += __shfl_xor_sync(0xffffffffu, rs, 2);
        rs += __shfl_xor_sync(0xffffffffu, rs, 1);
        if ((lane & 15) == 0)
            atomicAdd(&g_rowsum[b * LQ + q], rs);
    }
}

// ---------------------------------------------------------------------------
// Phase 2: normalize each row by its sum (memory bound).
// ---------------------------------------------------------------------------
__global__ __launch_bounds__(256)
void norm_kernel(float* __restrict__ out)
{
    const int row = blockIdx.x;            // 0 .. BATCH*LQ-1
    __shared__ float inv_s;
    if (threadIdx.x == 0) inv_s = 1.0f / g_rowsum[row];
    __syncthreads();
    const float inv = inv_s;

    float4* p = (float4*)(out + (size_t)row * LK);
#pragma unroll
    for (int i = 0; i < 4; ++i) {
        int idx = threadIdx.x + i * 256;
        float4 v = p[idx];
        v.x *= inv; v.y *= inv; v.z *= inv; v.w *= inv;
        p[idx] = v;
    }
}

// ---------------------------------------------------------------------------
// launch
// ---------------------------------------------------------------------------
extern "C" void kernel_launch(void* const* d_in, const int* in_sizes, int n_in,
                              void* d_out, int out_size)
{
    (void)in_sizes; (void)n_in; (void)out_size;
    const float* query = (const float*)d_in[0];
    const float* key   = (const float*)d_in[1];
    const int*   mask  = (const int*)  d_in[2];
    const float* Wq    = (const float*)d_in[3];
    const float* bq    = (const float*)d_in[4];
    const float* Wk    = (const float*)d_in[5];
    const float* bk    = (const float*)d_in[6];
    float* out = (float*)d_out;

    cudaFuncSetAttribute(attn_kernel,
                         cudaFuncAttributeMaxDynamicSharedMemorySize, 96 * 1024);

    zero_rowsum_kernel<<<8, 1024>>>();
    proj_kernel<<<(BATCH * LQ) / 64, 256>>>(query, Wq, bq, 0);
    proj_kernel<<<(BATCH * LK) / 64, 256>>>(key,   Wk, bk, 1);

    dim3 grid(LK / 64, LQ / 128, BATCH);
    attn_kernel<<<grid, 256, 96 * 1024>>>(mask, out);

    norm_kernel<<<BATCH * LQ, 256>>>(out);
}

// round 6
// speedup vs baseline: 3.5893x; 1.0107x over previous
#include <cuda_runtime.h>
#include <cuda_bf16.h>
#include <stdint.h>

#define BATCH 16
#define LQ    512
#define LK    4096
#define DM    128

// y = 2*log2(e) * s  so that 2^y = e^{2s}
#define TWO_LOG2E 2.8853900817779268f
// C*log2(e), C = 10/sqrt(128)
#define Z_SCALE   1.2751743093739637f

#define NGRP (BATCH * (LQ / 128))   // 64 (b, q-tile) groups
#define KCTAS (LK / 64)             // 64 k-CTAs per group

// Scratch (device globals; allocation is forbidden).
__device__ __align__(16) float g_kproj[(size_t)BATCH * LK * DM];   // 33.5 MB
__device__ __align__(16) float g_qproj[(size_t)BATCH * LQ * DM];   // 4 MB
__device__ float    g_rowsum[BATCH * LQ];
__device__ unsigned g_cnt[NGRP];

typedef unsigned long long ull;

// ---------------------------------------------------------------------------
// packed f32x2 helpers
// ---------------------------------------------------------------------------
__device__ __forceinline__ void fma2(ull& d, ull a, ull b) {
    asm("fma.rn.f32x2 %0, %1, %2, %0;" : "+l"(d) : "l"(a), "l"(b));
}
__device__ __forceinline__ ull fma2v(ull a, ull b, ull c) {
    ull d; asm("fma.rn.f32x2 %0, %1, %2, %3;" : "=l"(d) : "l"(a), "l"(b), "l"(c));
    return d;
}
__device__ __forceinline__ ull mul2v(ull a, ull b) {
    ull d; asm("mul.rn.f32x2 %0, %1, %2;" : "=l"(d) : "l"(a), "l"(b)); return d;
}
__device__ __forceinline__ ull add2v(ull a, ull b) {
    ull d; asm("add.rn.f32x2 %0, %1, %2;" : "=l"(d) : "l"(a), "l"(b)); return d;
}
__device__ __forceinline__ float2 unpack2(ull u) {
    float2 f;
    asm("mov.b64 {%0, %1}, %2;" : "=f"(f.x), "=f"(f.y) : "l"(u));
    return f;
}
__device__ __forceinline__ ull pack2(float a, float b) {
    ull u; asm("mov.b64 %0, {%1, %2};" : "=l"(u) : "f"(a), "f"(b)); return u;
}
__device__ __forceinline__ ull make2(float v) {          // compile-time foldable
    unsigned u = __float_as_uint(v);
    return ((ull)u << 32) | (ull)u;
}

// packed exp2, valid |y| <~ 120, rel err ~1e-7; runs on fma/alu pipes only
__device__ __forceinline__ ull exp2_2(ull y2) {
    const ull MAGIC2  = make2(12582912.0f);
    const ull NMAGIC2 = make2(-12582912.0f);
    const ull NEG1_2  = make2(-1.0f);
    ull t2  = add2v(y2, MAGIC2);
    float2 t = unpack2(t2);
    int e0 = (__float_as_int(t.x) - 0x4B400000) << 23;
    int e1 = (__float_as_int(t.y) - 0x4B400000) << 23;
    ull tm2 = add2v(t2, NMAGIC2);
    ull f2  = fma2v(tm2, NEG1_2, y2);              // f = y - round(y)
    ull p2  = make2(1.3333558146e-3f);
    p2 = fma2v(p2, f2, make2(9.6181291076e-3f));
    p2 = fma2v(p2, f2, make2(5.5504108664e-2f));
    p2 = fma2v(p2, f2, make2(2.4022650696e-1f));
    p2 = fma2v(p2, f2, make2(6.9314718056e-1f));
    p2 = fma2v(p2, f2, make2(1.0f));
    float2 p = unpack2(p2);
    float r0 = __int_as_float(__float_as_int(p.x) + e0);
    float r1 = __int_as_float(__float_as_int(p.y) + e1);
    return pack2(r0, r1);
}

// packed 1/a (a > 0 normal): bit-trick seed + 3 Newton (err ~1e-10)
__device__ __forceinline__ ull rcp2(ull a2) {
    const ull TWO2  = make2(2.0f);
    const ull NEG1_2 = make2(-1.0f);
    float2 a = unpack2(a2);
    float x0 = __int_as_float(0x7EF311C3 - __float_as_int(a.x));
    float x1 = __int_as_float(0x7EF311C3 - __float_as_int(a.y));
    ull x2  = pack2(x0, x1);
    ull na2 = mul2v(a2, NEG1_2);
    ull e2;
    e2 = fma2v(na2, x2, TWO2); x2 = mul2v(x2, e2);
    e2 = fma2v(na2, x2, TWO2); x2 = mul2v(x2, e2);
    e2 = fma2v(na2, x2, TWO2); x2 = mul2v(x2, e2);
    return x2;
}

// packed exp(C*tanh(s)) for two scores, zero MUFU:
//   tanh(s) = 1 - 2/(1 + 2^{2 log2e s})
__device__ __forceinline__ ull attn_weight2(float s0, float s1) {
    const ull ONE2 = make2(1.0f);
    float y0 = fminf(fmaxf(TWO_LOG2E * s0, -30.0f), 30.0f);
    float y1 = fminf(fmaxf(TWO_LOG2E * s1, -30.0f), 30.0f);
    ull u2 = exp2_2(pack2(y0, y1));
    ull r2 = rcp2(add2v(u2, ONE2));
    ull t2 = fma2v(r2, make2(-2.0f), ONE2);        // tanh
    return exp2_2(mul2v(t2, make2(Z_SCALE)));
}

// scalar fast reciprocal for the final row-sum normalization
__device__ __forceinline__ float fast_rcp(float a) {
    float x = __int_as_float(0x7EF311C3 - __float_as_int(a));
    x = x * fmaf(-a, x, 2.0f);
    x = x * fmaf(-a, x, 2.0f);
    x = x * fmaf(-a, x, 2.0f);
    return x;
}

// ---------------------------------------------------------------------------
// zero the cross-CTA accumulators (graph replays re-enter with stale values)
// ---------------------------------------------------------------------------
__global__ void zero_kernel() {
    int i = blockIdx.x * blockDim.x + threadIdx.x;
    if (i < BATCH * LQ) g_rowsum[i] = 0.0f;
    if (i < NGRP)       g_cnt[i]    = 0u;
}

// ---------------------------------------------------------------------------
// Merged projection: one launch covers q (first 128 CTAs) and k (next 1024).
// Y[m][e] = sum_d X[m][d] * W[d][e] + b[e]
// ---------------------------------------------------------------------------
__global__ __launch_bounds__(256)
void proj_kernel(const float* __restrict__ Q, const float* __restrict__ Wq,
                 const float* __restrict__ bq,
                 const float* __restrict__ K, const float* __restrict__ Wk,
                 const float* __restrict__ bk)
{
    const bool is_q = blockIdx.x < (BATCH * LQ) / 64;
    const float* __restrict__ X    = is_q ? Q  : K;
    const float* __restrict__ W    = is_q ? Wq : Wk;
    const float* __restrict__ bias = is_q ? bq : bk;
    float* __restrict__ Y          = is_q ? g_qproj : g_kproj;
    const int m0 = (is_q ? blockIdx.x : blockIdx.x - (BATCH * LQ) / 64) * 64;

    __shared__ __align__(16) float Xs[64 * 132];
    const int tid = threadIdx.x;

#pragma unroll
    for (int i = 0; i < 8; ++i) {
        int idx = tid + i * 256;
        int m   = idx >> 5;
        int d4  = idx & 31;
        float4 v = *(const float4*)(X + (size_t)(m0 + m) * DM + d4 * 4);
        *(float4*)(Xs + m * 132 + d4 * 4) = v;
    }
    __syncthreads();

    const int tx = tid & 15;
    const int ty = tid >> 4;
    const int c0 = tx * 8;

    float acc[4][8];
#pragma unroll
    for (int r = 0; r < 4; ++r)
#pragma unroll
        for (int c = 0; c < 8; ++c) acc[r][c] = 0.0f;

    for (int d4 = 0; d4 < 32; ++d4) {
        const int d = d4 * 4;
        float4 w0[4], w1[4];
#pragma unroll
        for (int j = 0; j < 4; ++j) {
            w0[j] = *(const float4*)(W + (size_t)(d + j) * DM + c0);
            w1[j] = *(const float4*)(W + (size_t)(d + j) * DM + c0 + 4);
        }
#pragma unroll
        for (int r = 0; r < 4; ++r) {
            float4 x4 = *(const float4*)(Xs + (ty * 4 + r) * 132 + d);
            float xv[4] = {x4.x, x4.y, x4.z, x4.w};
#pragma unroll
            for (int j = 0; j < 4; ++j) {
                acc[r][0] += xv[j] * w0[j].x;
                acc[r][1] += xv[j] * w0[j].y;
                acc[r][2] += xv[j] * w0[j].z;
                acc[r][3] += xv[j] * w0[j].w;
                acc[r][4] += xv[j] * w1[j].x;
                acc[r][5] += xv[j] * w1[j].y;
                acc[r][6] += xv[j] * w1[j].z;
                acc[r][7] += xv[j] * w1[j].w;
            }
        }
    }

    float4 b0 = *(const float4*)(bias + c0);
    float4 b1 = *(const float4*)(bias + c0 + 4);
#pragma unroll
    for (int r = 0; r < 4; ++r) {
        size_t row = (size_t)(m0 + ty * 4 + r) * DM;
        float4 o0 = make_float4(acc[r][0] + b0.x, acc[r][1] + b0.y,
                                acc[r][2] + b0.z, acc[r][3] + b0.w);
        float4 o1 = make_float4(acc[r][4] + b1.x, acc[r][5] + b1.y,
                                acc[r][6] + b1.z, acc[r][7] + b1.w);
        *(float4*)(Y + row + c0)     = o0;
        *(float4*)(Y + row + c0 + 4) = o1;
    }
}

// ---------------------------------------------------------------------------
// Fused attention: register-tiled f32x2 GEMM + packed MUFU-free epilogue +
// cross-CTA row-sum handshake + in-register normalization (no norm pass).
// CTA tile 128q x 64k; thread (tx,ty) owns 8 q-rows x 4 k-cols (stride 16).
// ---------------------------------------------------------------------------
__global__ __launch_bounds__(256, 2)
void attn_kernel(const int* __restrict__ mask, float* __restrict__ out)
{
    extern __shared__ float4 smem4[];
    float4* Qs = smem4;              // [128][32] f4, col j at j^((row>>3)&7)
    float4* Ks = smem4 + 128 * 32;   // [64][32]  f4, col j at j^(row&7)

    const int b   = blockIdx.z;
    const int q0  = blockIdx.y * 128;
    const int n0  = blockIdx.x * 64;
    const int tid = threadIdx.x;
    const int tx  = tid & 15;
    const int ty  = tid >> 4;

    const float4* qsrc = (const float4*)(g_qproj + ((size_t)b * LQ + q0) * DM);
    const float4* ksrc = (const float4*)(g_kproj + ((size_t)b * LK + n0) * DM);
#pragma unroll
    for (int i = 0; i < 24; ++i) {
        int idx = tid + i * 256;
        int row = idx >> 5;
        int j   = idx & 31;
        if (row < 128) {
            Qs[row * 32 + (j ^ ((row >> 3) & 7))] = qsrc[row * 32 + j];
        } else {
            int kr = row - 128;
            Ks[kr * 32 + (j ^ (kr & 7))] = ksrc[kr * 32 + j];
        }
    }
    __syncthreads();

    // ---- GEMM (d-packed f32x2) ----
    ull acc[8][4];
#pragma unroll
    for (int r = 0; r < 8; ++r)
#pragma unroll
        for (int c = 0; c < 4; ++c) acc[r][c] = 0ull;

    const int sq = ty & 7;
    const int sk = tx & 7;
    const float4* qbase = Qs + (ty * 8) * 32;
    const float4* kbase = Ks + tx * 32;

#pragma unroll 4
    for (int d4 = 0; d4 < 32; ++d4) {
        const int dq = d4 ^ sq;
        const int dk = d4 ^ sk;
        ulonglong2 kv[4];
#pragma unroll
        for (int c = 0; c < 4; ++c)
            kv[c] = *(const ulonglong2*)(kbase + c * 512 + dk);
#pragma unroll
        for (int r = 0; r < 8; ++r) {
            ulonglong2 qv = *(const ulonglong2*)(qbase + r * 32 + dq);
#pragma unroll
            for (int c = 0; c < 4; ++c) {
                fma2(acc[r][c], qv.x, kv[c].x);
                fma2(acc[r][c], qv.y, kv[c].y);
            }
        }
    }

    // ---- epilogue: packed weights, mask, keep e in registers, row sums ----
    const int lane = tid & 31;
    float ev[8][4];
#pragma unroll
    for (int r = 0; r < 8; ++r) {
        const int    q     = q0 + ty * 8 + r;
        const size_t obase = ((size_t)b * LQ + q) * LK + n0 + tx;
        float rs = 0.0f;
#pragma unroll
        for (int cp = 0; cp < 2; ++cp) {
            float2 pa = unpack2(acc[r][2 * cp]);
            float2 pb = unpack2(acc[r][2 * cp + 1]);
            float2 w  = unpack2(attn_weight2(pa.x + pa.y, pb.x + pb.y));
            float e0 = (mask[obase + (size_t)(2 * cp)     * 16] != 0) ? w.x : 0.0f;
            float e1 = (mask[obase + (size_t)(2 * cp + 1) * 16] != 0) ? w.y : 0.0f;
            ev[r][2 * cp]     = e0;
            ev[r][2 * cp + 1] = e1;
            rs += e0 + e1;
        }
        rs += __shfl_xor_sync(0xffffffffu, rs, 8);
        rs += __shfl_xor_sync(0xffffffffu, rs, 4);
        rs += __shfl_xor_sync(0xffffffffu, rs, 2);
        rs += __shfl_xor_sync(0xffffffffu, rs, 1);
        if ((lane & 15) == 0)
            atomicAdd(&g_rowsum[b * LQ + q], rs);
    }

    // ---- cross-CTA handshake: wait for all 64 k-CTAs of this row group ----
    const int grp = b * (LQ / 128) + blockIdx.y;
    __threadfence();
    __syncthreads();
    if (tid == 0) {
        atomicAdd(&g_cnt[grp], 1u);
        unsigned v;
        do {
            asm volatile("ld.global.acquire.gpu.b32 %0, [%1];"
                         : "=r"(v) : "l"(g_cnt + grp) : "memory");
        } while (v < KCTAS);
    }
    __syncthreads();

    // ---- normalize in registers and store ----
#pragma unroll
    for (int r = 0; r < 8; ++r) {
        const int    q     = q0 + ty * 8 + r;
        const size_t obase = ((size_t)b * LQ + q) * LK + n0 + tx;
        float inv = fast_rcp(__ldcg(&g_rowsum[b * LQ + q]));
#pragma unroll
        for (int c = 0; c < 4; ++c)
            out[obase + (size_t)c * 16] = ev[r][c] * inv;
    }
}

// ---------------------------------------------------------------------------
// launch
// ---------------------------------------------------------------------------
extern "C" void kernel_launch(void* const* d_in, const int* in_sizes, int n_in,
                              void* d_out, int out_size)
{
    (void)in_sizes; (void)n_in; (void)out_size;
    const float* query = (const float*)d_in[0];
    const float* key   = (const float*)d_in[1];
    const int*   mask  = (const int*)  d_in[2];
    const float* Wq    = (const float*)d_in[3];
    const float* bq    = (const float*)d_in[4];
    const float* Wk    = (const float*)d_in[5];
    const float* bk    = (const float*)d_in[6];
    float* out = (float*)d_out;

    cudaFuncSetAttribute(attn_kernel,
                         cudaFuncAttributeMaxDynamicSharedMemorySize, 96 * 1024);

    zero_kernel<<<32, 256>>>();
    proj_kernel<<<(BATCH * LQ) / 64 + (BATCH * LK) / 64, 256>>>(
        query, Wq, bq, key, Wk, bk);

    dim3 grid(LK / 64, LQ / 128, BATCH);
    attn_kernel<<<grid, 256, 96 * 1024>>>(mask, out);
}

// round 9
// speedup vs baseline: 5.1730x; 1.4413x over previous
#include <cuda_runtime.h>
#include <cuda_bf16.h>
#include <stdint.h>

#define BATCH 16
#define LQ    512
#define LK    4096
#define DM    128

#define TWO_LOG2E 2.8853900817779268f
#define Z_SCALE   1.2751743093739637f

typedef unsigned long long ull;

// ---------------- device scratch (no allocation allowed) ----------------
__device__ __align__(16) __nv_bfloat16 g_qh[(size_t)BATCH * LQ * DM];
__device__ __align__(16) __nv_bfloat16 g_ql[(size_t)BATCH * LQ * DM];
__device__ __align__(16) __nv_bfloat16 g_kh[(size_t)BATCH * LK * DM];
__device__ __align__(16) __nv_bfloat16 g_kl[(size_t)BATCH * LK * DM];
__device__ float    g_rowsum[BATCH * LQ];
__device__ unsigned g_cnt[BATCH * (LQ / 128)];

// ---------------- PTX helpers (baseline sm_80+ features only) ----------------
__device__ __forceinline__ uint32_t smem_u32(const void* p) {
    uint32_t a;
    asm("{ .reg .u64 t; cvta.to.shared.u64 t, %1; cvt.u32.u64 %0, t; }"
        : "=r"(a) : "l"(p));
    return a;
}
__device__ __forceinline__ void cp16(uint32_t dst, const void* src) {
    asm volatile("cp.async.cg.shared.global [%0], [%1], 16;"
                 :: "r"(dst), "l"(src) : "memory");
}
#define CP_COMMIT() asm volatile("cp.async.commit_group;" ::: "memory")
#define CP_WAIT0()  asm volatile("cp.async.wait_group 0;" ::: "memory")

__device__ __forceinline__ void ldsm4(uint32_t& r0, uint32_t& r1,
                                      uint32_t& r2, uint32_t& r3, uint32_t a) {
    asm volatile("ldmatrix.sync.aligned.m8n8.x4.shared.b16 {%0,%1,%2,%3}, [%4];"
                 : "=r"(r0), "=r"(r1), "=r"(r2), "=r"(r3) : "r"(a));
}
__device__ __forceinline__ void mma_bf16(float* d, const uint32_t* a,
                                         const uint32_t* b) {
    asm volatile(
        "mma.sync.aligned.m16n8k16.row.col.f32.bf16.bf16.f32 "
        "{%0,%1,%2,%3}, {%4,%5,%6,%7}, {%8,%9}, {%0,%1,%2,%3};"
        : "+f"(d[0]), "+f"(d[1]), "+f"(d[2]), "+f"(d[3])
        : "r"(a[0]), "r"(a[1]), "r"(a[2]), "r"(a[3]), "r"(b[0]), "r"(b[1]));
}

// ---------------- packed f32x2 math (MUFU-free transcendentals) ----------------
__device__ __forceinline__ ull fma2v(ull a, ull b, ull c) {
    ull d; asm("fma.rn.f32x2 %0, %1, %2, %3;" : "=l"(d) : "l"(a), "l"(b), "l"(c));
    return d;
}
__device__ __forceinline__ ull mul2v(ull a, ull b) {
    ull d; asm("mul.rn.f32x2 %0, %1, %2;" : "=l"(d) : "l"(a), "l"(b)); return d;
}
__device__ __forceinline__ ull add2v(ull a, ull b) {
    ull d; asm("add.rn.f32x2 %0, %1, %2;" : "=l"(d) : "l"(a), "l"(b)); return d;
}
__device__ __forceinline__ float2 unpack2(ull u) {
    float2 f; asm("mov.b64 {%0, %1}, %2;" : "=f"(f.x), "=f"(f.y) : "l"(u)); return f;
}
__device__ __forceinline__ ull pack2(float a, float b) {
    ull u; asm("mov.b64 %0, {%1, %2};" : "=l"(u) : "f"(a), "f"(b)); return u;
}
__device__ __forceinline__ ull make2(float v) {
    unsigned u = __float_as_uint(v);
    return ((ull)u << 32) | (ull)u;
}

__device__ __forceinline__ ull exp2_2(ull y2) {
    ull t2 = add2v(y2, make2(12582912.0f));
    float2 t = unpack2(t2);
    int e0 = (__float_as_int(t.x) - 0x4B400000) << 23;
    int e1 = (__float_as_int(t.y) - 0x4B400000) << 23;
    ull tm2 = add2v(t2, make2(-12582912.0f));
    ull f2  = fma2v(tm2, make2(-1.0f), y2);
    ull p2  = make2(1.3333558146e-3f);
    p2 = fma2v(p2, f2, make2(9.6181291076e-3f));
    p2 = fma2v(p2, f2, make2(5.5504108664e-2f));
    p2 = fma2v(p2, f2, make2(2.4022650696e-1f));
    p2 = fma2v(p2, f2, make2(6.9314718056e-1f));
    p2 = fma2v(p2, f2, make2(1.0f));
    float2 p = unpack2(p2);
    return pack2(__int_as_float(__float_as_int(p.x) + e0),
                 __int_as_float(__float_as_int(p.y) + e1));
}
__device__ __forceinline__ ull rcp2(ull a2) {
    float2 a = unpack2(a2);
    float x0 = __int_as_float(0x7EF311C3 - __float_as_int(a.x));
    float x1 = __int_as_float(0x7EF311C3 - __float_as_int(a.y));
    ull x2  = pack2(x0, x1);
    ull na2 = mul2v(a2, make2(-1.0f));
    ull e2;
    e2 = fma2v(na2, x2, make2(2.0f)); x2 = mul2v(x2, e2);
    e2 = fma2v(na2, x2, make2(2.0f)); x2 = mul2v(x2, e2);
    e2 = fma2v(na2, x2, make2(2.0f)); x2 = mul2v(x2, e2);
    return x2;
}
// exp(C*tanh(s)) for two scores:  tanh(s) = 1 - 2/(1 + 2^{2 log2e s})
__device__ __forceinline__ ull attn_weight2(float s0, float s1) {
    float y0 = fminf(fmaxf(TWO_LOG2E * s0, -30.0f), 30.0f);
    float y1 = fminf(fmaxf(TWO_LOG2E * s1, -30.0f), 30.0f);
    ull u2 = exp2_2(pack2(y0, y1));
    ull r2 = rcp2(add2v(u2, make2(1.0f)));
    ull t2 = fma2v(r2, make2(-2.0f), make2(1.0f));
    return exp2_2(mul2v(t2, make2(Z_SCALE)));
}
__device__ __forceinline__ float fast_rcp(float a) {
    float x = __int_as_float(0x7EF311C3 - __float_as_int(a));
    x = x * fmaf(-a, x, 2.0f);
    x = x * fmaf(-a, x, 2.0f);
    x = x * fmaf(-a, x, 2.0f);
    return x;
}

// ---------------------------------------------------------------------------
// zero accumulators (graph replays re-enter with stale values)
// ---------------------------------------------------------------------------
__global__ void zero_kernel() {
    int i = blockIdx.x * blockDim.x + threadIdx.x;
    if (i < BATCH * LQ) g_rowsum[i] = 0.0f;
    if (i < BATCH * (LQ / 128)) g_cnt[i] = 0u;
}

// ---------------------------------------------------------------------------
// Merged projection, packed f32x2; writes bf16 hi/lo split arrays.
// ---------------------------------------------------------------------------
__global__ __launch_bounds__(256)
void proj_kernel(const float* __restrict__ Q, const float* __restrict__ Wq,
                 const float* __restrict__ bq,
                 const float* __restrict__ K, const float* __restrict__ Wk,
                 const float* __restrict__ bk)
{
    const bool is_q = blockIdx.x < (BATCH * LQ) / 64;
    const float* __restrict__ X    = is_q ? Q  : K;
    const float* __restrict__ W    = is_q ? Wq : Wk;
    const float* __restrict__ bias = is_q ? bq : bk;
    __nv_bfloat16* __restrict__ Yh = is_q ? g_qh : g_kh;
    __nv_bfloat16* __restrict__ Yl = is_q ? g_ql : g_kl;
    const int m0 = (is_q ? blockIdx.x : blockIdx.x - (BATCH * LQ) / 64) * 64;

    __shared__ __align__(16) float Xs[64 * 132];
    const int tid = threadIdx.x;

#pragma unroll
    for (int i = 0; i < 8; ++i) {
        int idx = tid + i * 256;
        int m   = idx >> 5;
        int d4  = idx & 31;
        float4 v = *(const float4*)(X + (size_t)(m0 + m) * DM + d4 * 4);
        *(float4*)(Xs + m * 132 + d4 * 4) = v;
    }
    __syncthreads();

    const int tx = tid & 15;
    const int ty = tid >> 4;
    const int c0 = tx * 8;

    ull acc[4][4];
#pragma unroll
    for (int r = 0; r < 4; ++r)
#pragma unroll
        for (int p = 0; p < 4; ++p) acc[r][p] = 0ull;

    for (int d4 = 0; d4 < 32; ++d4) {
        const int d = d4 * 4;
        ulonglong2 wv[4][2];
#pragma unroll
        for (int j = 0; j < 4; ++j) {
            const ulonglong2* wp =
                (const ulonglong2*)(W + (size_t)(d + j) * DM + c0);
            wv[j][0] = wp[0];
            wv[j][1] = wp[1];
        }
#pragma unroll
        for (int r = 0; r < 4; ++r) {
            float4 x4 = *(const float4*)(Xs + (ty * 4 + r) * 132 + d);
            float xv[4] = {x4.x, x4.y, x4.z, x4.w};
#pragma unroll
            for (int j = 0; j < 4; ++j) {
                ull xb = pack2(xv[j], xv[j]);
                acc[r][0] = fma2v(xb, wv[j][0].x, acc[r][0]);
                acc[r][1] = fma2v(xb, wv[j][0].y, acc[r][1]);
                acc[r][2] = fma2v(xb, wv[j][1].x, acc[r][2]);
                acc[r][3] = fma2v(xb, wv[j][1].y, acc[r][3]);
            }
        }
    }

    const ull* bp = (const ull*)(bias + c0);
    ull bb[4] = {bp[0], bp[1], bp[2], bp[3]};
#pragma unroll
    for (int r = 0; r < 4; ++r) {
        size_t row = (size_t)(m0 + ty * 4 + r) * DM;
        union { __nv_bfloat16 h[8]; uint4 v; } uh, ul;
#pragma unroll
        for (int p = 0; p < 4; ++p) {
            float2 a = unpack2(add2v(acc[r][p], bb[p]));
            __nv_bfloat16 h0 = __float2bfloat16_rn(a.x);
            __nv_bfloat16 h1 = __float2bfloat16_rn(a.y);
            uh.h[2 * p]     = h0;
            uh.h[2 * p + 1] = h1;
            ul.h[2 * p]     = __float2bfloat16_rn(a.x - __bfloat162float(h0));
            ul.h[2 * p + 1] = __float2bfloat16_rn(a.y - __bfloat162float(h1));
        }
        *(uint4*)(Yh + row + c0) = uh.v;
        *(uint4*)(Yl + row + c0) = ul.v;
    }
}

// ---------------------------------------------------------------------------
// Attention: mma.sync bf16 3-split (hh + hl + lh), D rows = q, cols = k.
// CTA = 128q x 2048k; 16 k-tiles of 128, cp.async double-buffered K staging.
// smem: Q hi/lo @0/32768 (32KB each); K bufs @65536 + buf*65536 (hi/lo 32KB).
// Row layout: 128 rows x 256B, 16B chunks swizzled c^(row&7).
// B fragments use NON-transposed ldmatrix: K smem rows = tokens give each
// lane two consecutive d of one token, exactly the m16n8k16 B layout.
// ---------------------------------------------------------------------------
__global__ __launch_bounds__(256, 1)
void attn_kernel(const int* __restrict__ mask, float* __restrict__ out)
{
    extern __shared__ __align__(1024) char smem[];
    const uint32_t su = smem_u32(smem);
    const int tid   = threadIdx.x;
    const int wid   = tid >> 5;
    const int lane  = tid & 31;
    const int khalf = blockIdx.x;           // 0/1
    const int qy    = blockIdx.y;           // 0..3
    const int b     = blockIdx.z;
    const int q0    = qy * 128;

    // ---- stage Q (once) + K tile 0, all via cp.async ----
    {
        const __nv_bfloat16* qh = g_qh + ((size_t)b * LQ + q0) * DM;
        const __nv_bfloat16* ql = g_ql + ((size_t)b * LQ + q0) * DM;
        const __nv_bfloat16* kh = g_kh + ((size_t)b * LK + khalf * 2048) * DM;
        const __nv_bfloat16* kl = g_kl + ((size_t)b * LK + khalf * 2048) * DM;
#pragma unroll
        for (int i = 0; i < 8; ++i) {
            int idx = tid + i * 256;        // 16B chunk index, 2048 per tile
            int row = idx >> 4, c = idx & 15;
            uint32_t d = (uint32_t)(row * 256 + ((c ^ (row & 7)) << 4));
            cp16(su + d,                 qh + idx * 8);
            cp16(su + 32768 + d,         ql + idx * 8);
            cp16(su + 65536 + d,         kh + idx * 8);
            cp16(su + 65536 + 32768 + d, kl + idx * 8);
        }
        CP_COMMIT();
    }

    // warp tiling: wq = wid&3 -> 32 q-rows; wk = wid>>2 -> 64 k-cols
    const int q_off = (wid & 3) * 32;
    const int n_off = (wid >> 2) * 64;
    const int rsw   = lane & 7;
    const uint32_t aOff0 = (uint32_t)((q_off + (lane & 15)) * 256);
    const uint32_t aOff1 = aOff0 + 16 * 256;
    const int aSel = (lane >> 4) & 1;
    const uint32_t bOff =
        (uint32_t)((n_off + ((lane >> 4) & 1) * 8 + (lane & 7)) * 256);
    const int bSel = (lane >> 3) & 1;
    const int g   = lane >> 2;
    const int tig = lane & 3;

    float rs[2][2] = {{0.0f, 0.0f}, {0.0f, 0.0f}};

    for (int t = 0; t < 16; ++t) {
        CP_WAIT0();
        __syncthreads();

        // prefetch tile t+1 into the other buffer (overlaps compute of t)
        if (t < 15) {
            const __nv_bfloat16* kh =
                g_kh + ((size_t)b * LK + khalf * 2048 + (t + 1) * 128) * DM;
            const __nv_bfloat16* kl =
                g_kl + ((size_t)b * LK + khalf * 2048 + (t + 1) * 128) * DM;
            uint32_t base = su + 65536 + (uint32_t)(((t + 1) & 1) * 65536);
#pragma unroll
            for (int i = 0; i < 8; ++i) {
                int idx = tid + i * 256;
                int row = idx >> 4, c = idx & 15;
                uint32_t d = (uint32_t)(row * 256 + ((c ^ (row & 7)) << 4));
                cp16(base + d,         kh + idx * 8);
                cp16(base + 32768 + d, kl + idx * 8);
            }
            CP_COMMIT();
        }

        const uint32_t kbuf = su + 65536 + (uint32_t)((t & 1) * 65536);

        float acc[2][8][4];
#pragma unroll
        for (int i = 0; i < 2; ++i)
#pragma unroll
            for (int j = 0; j < 8; ++j)
#pragma unroll
                for (int v = 0; v < 4; ++v) acc[i][j][v] = 0.0f;

#pragma unroll 2
        for (int dc = 0; dc < 8; ++dc) {
            uint32_t ah[2][4], al[2][4], bh[8][2], bl[8][2];
            const uint32_t ca = (uint32_t)(((dc * 2 + aSel) ^ rsw) << 4);
            ldsm4(ah[0][0], ah[0][1], ah[0][2], ah[0][3], su + aOff0 + ca);
            ldsm4(ah[1][0], ah[1][1], ah[1][2], ah[1][3], su + aOff1 + ca);
            ldsm4(al[0][0], al[0][1], al[0][2], al[0][3],
                  su + 32768 + aOff0 + ca);
            ldsm4(al[1][0], al[1][1], al[1][2], al[1][3],
                  su + 32768 + aOff1 + ca);
            const uint32_t cb = (uint32_t)(((dc * 2 + bSel) ^ rsw) << 4);
#pragma unroll
            for (int jp = 0; jp < 4; ++jp) {
                uint32_t addr = kbuf + bOff + (uint32_t)(jp * 4096) + cb;
                ldsm4(bh[2 * jp][0], bh[2 * jp][1],
                      bh[2 * jp + 1][0], bh[2 * jp + 1][1], addr);
                ldsm4(bl[2 * jp][0], bl[2 * jp][1],
                      bl[2 * jp + 1][0], bl[2 * jp + 1][1], addr + 32768);
            }
#pragma unroll
            for (int i = 0; i < 2; ++i)
#pragma unroll
                for (int j = 0; j < 8; ++j) {
                    mma_bf16(acc[i][j], ah[i], bh[j]);   // hi*hi
                    mma_bf16(acc[i][j], ah[i], bl[j]);   // hi*lo
                    mma_bf16(acc[i][j], al[i], bh[j]);   // lo*hi
                }
        }

        // ---- epilogue: weights, mask, store, register row sums ----
        const size_t brow = (size_t)(b * LQ + q0 + q_off);
        const int    nb   = khalf * 2048 + t * 128 + n_off + 2 * tig;
#pragma unroll
        for (int i = 0; i < 2; ++i) {
            const size_t r0 = (brow + 16 * i + g) * LK;
#pragma unroll
            for (int j = 0; j < 8; ++j) {
                size_t i0 = r0 + (size_t)(nb + 8 * j);
                size_t i1 = i0 + (size_t)8 * LK;
                float2 w01 = unpack2(attn_weight2(acc[i][j][0], acc[i][j][1]));
                float2 w23 = unpack2(attn_weight2(acc[i][j][2], acc[i][j][3]));
                int2 m0 = *(const int2*)(mask + i0);
                int2 m1 = *(const int2*)(mask + i1);
                float e0 = m0.x ? w01.x : 0.0f;
                float e1 = m0.y ? w01.y : 0.0f;
                float e2 = m1.x ? w23.x : 0.0f;
                float e3 = m1.y ? w23.y : 0.0f;
                *(float2*)(out + i0) = make_float2(e0, e1);
                *(float2*)(out + i1) = make_float2(e2, e3);
                rs[i][0] += e0 + e1;
                rs[i][1] += e2 + e3;
            }
        }
        __syncthreads();    // all reads of kbuf done before it is restaged
    }

    // ---- row sums: quad-reduce then atomicAdd ----
#pragma unroll
    for (int i = 0; i < 2; ++i)
#pragma unroll
        for (int h = 0; h < 2; ++h) {
            float v = rs[i][h];
            v += __shfl_xor_sync(0xffffffffu, v, 1);
            v += __shfl_xor_sync(0xffffffffu, v, 2);
            if (tig == 0)
                atomicAdd(&g_rowsum[b * LQ + q0 + q_off + 16 * i + 8 * h + g], v);
        }
    __syncthreads();

    // ---- 2-CTA handshake (128 CTAs, single wave -> co-resident) ----
    if (tid == 0) {
        __threadfence();
        const int grp = b * (LQ / 128) + qy;
        atomicAdd(&g_cnt[grp], 1u);
        unsigned v;
        do {
            asm volatile("ld.global.acquire.gpu.b32 %0, [%1];"
                         : "=r"(v) : "l"(g_cnt + grp) : "memory");
        } while (v < 2);
    }
    __syncthreads();

    // ---- normalize own half (L1/L2-hot re-read) ----
#pragma unroll
    for (int rr = 0; rr < 16; ++rr) {
        int q_g = q0 + wid * 16 + rr;
        float inv = fast_rcp(__ldcg(&g_rowsum[b * LQ + q_g]));
        float4* rowp = (float4*)(out + ((size_t)(b * LQ) + q_g) * LK
                                 + (size_t)khalf * 2048);
#pragma unroll
        for (int it = 0; it < 16; ++it) {
            float4 v = rowp[lane + it * 32];
            v.x *= inv; v.y *= inv; v.z *= inv; v.w *= inv;
            rowp[lane + it * 32] = v;
        }
    }
}

// ---------------------------------------------------------------------------
// launch
// ---------------------------------------------------------------------------
extern "C" void kernel_launch(void* const* d_in, const int* in_sizes, int n_in,
                              void* d_out, int out_size)
{
    (void)in_sizes; (void)n_in; (void)out_size;
    const float* query = (const float*)d_in[0];
    const float* key   = (const float*)d_in[1];
    const int*   mask  = (const int*)  d_in[2];
    const float* Wq    = (const float*)d_in[3];
    const float* bq    = (const float*)d_in[4];
    const float* Wk    = (const float*)d_in[5];
    const float* bk    = (const float*)d_in[6];
    float* out = (float*)d_out;

    cudaFuncSetAttribute(attn_kernel,
                         cudaFuncAttributeMaxDynamicSharedMemorySize, 196608);

    zero_kernel<<<32, 256>>>();
    proj_kernel<<<(BATCH * LQ) / 64 + (BATCH * LK) / 64, 256>>>(
        query, Wq, bq, key, Wk, bk);

    dim3 grid(2, LQ / 128, BATCH);
    attn_kernel<<<grid, 256, 196608>>>(mask, out);
}